// round 9
// baseline (speedup 1.0000x reference)
#include <cuda_runtime.h>
#include <cuda_fp16.h>
#include <stdint.h>

#define B_TOT   16384
#define N_IN    6
#define N_MF    5
#define N_FUZZ  30
#define N_RULES 2048
#define NSPLIT  32
#define RPS     (N_RULES / NSPLIT)   // 64 rules per split
#define TPB     128
#define EPB     512                  // 4 elems per thread
#define NGROUP  (B_TOT / EPB)        // 32
#define EPS_F   1e-12f
#define SQRT_LOG2E 1.2011224087864498f   // sqrt(log2(e))

// Scratch (__device__ globals: no allocation allowed)
__device__ float4 g_partial[NSPLIT * B_TOT];   // {l1, d0, d1, pad}
__device__ int    g_cnt[NGROUP];               // zero-init; reset after use

// ---- packed f32x2 helpers ----
typedef unsigned long long u64;
static __device__ __forceinline__ u64 pack2(float lo, float hi) {
    u64 r; asm("mov.b64 %0, {%1, %2};" : "=l"(r) : "f"(lo), "f"(hi)); return r;
}
static __device__ __forceinline__ void unpack2(float& lo, float& hi, u64 v) {
    asm("mov.b64 {%0, %1}, %2;" : "=f"(lo), "=f"(hi) : "l"(v));
}
static __device__ __forceinline__ u64 add2(u64 a, u64 b) {
    u64 r; asm("add.rn.f32x2 %0, %1, %2;" : "=l"(r) : "l"(a), "l"(b)); return r;
}
static __device__ __forceinline__ u64 fma2(u64 a, u64 b, u64 c) {
    u64 r; asm("fma.rn.f32x2 %0, %1, %2, %3;" : "=l"(r) : "l"(a), "l"(b), "l"(c)); return r;
}
static __device__ __forceinline__ float ex2(float v) {
    float r; asm("ex2.approx.ftz.f32 %0, %1;" : "=f"(r) : "f"(v)); return r;
}

// ---------------------------------------------------------------------------
// Single fused kernel, 4 elems per thread.
//  - SMEM fuzz word (idx, t) = uint2 {h2(e0,e1), h2(e2,e3)}, e0 = base+4t.
//    One LDS.64 gather serves 4 elems. Lane l hits banks {2l, 2l+1} mod 32:
//    2 phases, conflict-free. Row stride 128*8B = 1024B.
//  - Per-rule metadata staged in SMEM unpacked: uint4 offs0-3 (LDS.128 bcast),
//    uint2 offs4-5 (LDS.64 bcast), ulonglong2 {ow0|ow0, ow1|ow1} (LDS.128
//    bcast, feeds f32x2 FMA directly, zero repack MOVs).
//    Broadcast cost amortizes over 128 elems/warp: 3 wf vs 12 gather wf.
//  - grid (NGROUP=32, NSPLIT=32) = 1024 blocks, RPS=64.
//  - Last-arriving split block per group finalizes (deterministic order).
// ---------------------------------------------------------------------------
__global__ __launch_bounds__(TPB) void anfis_fused_kernel(
    const float* __restrict__ x,
    const float* __restrict__ mf_centers,
    const float* __restrict__ mf_scales,
    const float* __restrict__ out_centers,
    const int*   __restrict__ input_rules,
    const int*   __restrict__ output_rules,
    float* __restrict__ out)
{
    __shared__ uint2      s_fuzz[N_FUZZ * TPB];  // 30 KB
    __shared__ uint4      s_pkA[RPS];            // 1 KB  offs0..3 (<<10)
    __shared__ uint2      s_pkB[RPS];            // 0.5 KB offs4..5 (<<10)
    __shared__ ulonglong2 s_owd[RPS];            // 1 KB  {ow0x2, ow1x2}
    __shared__ float2     s_cs[N_FUZZ];          // {c*a, a}
    __shared__ int        s_flag;

    const int tid   = threadIdx.x;
    const int grp   = blockIdx.x;
    const int split = blockIdx.y;
    const int base  = grp * EPB;
    const int e0    = base + 4 * tid;            // first of this thread's 4 elems

    // ---- stage this split's rules (unpacked; ow pre-duplicated) ----
    if (tid < RPS) {
        const int r = split * RPS + tid;
        const int* ir = input_rules + r * N_IN;
        float ow0 = out_centers[output_rules[r * 2 + 0]];
        float ow1 = out_centers[output_rules[r * 2 + 1]];
        s_pkA[tid] = make_uint4((unsigned)ir[0] << 10, (unsigned)ir[1] << 10,
                                (unsigned)ir[2] << 10, (unsigned)ir[3] << 10);
        s_pkB[tid] = make_uint2((unsigned)ir[4] << 10, (unsigned)ir[5] << 10);
        s_owd[tid] = make_ulonglong2(pack2(ow0, ow0), pack2(ow1, ow1));
    }
    // ---- membership-function constants: a = sqrt(log2e)/s ----
    if (tid < N_FUZZ) {
        float c = mf_centers[tid];
        float s = mf_scales[tid];
        float a = __fdividef(SQRT_LOG2E, s);
        s_cs[tid] = make_float2(c * a, a);
    }
    __syncthreads();

    // ---- fuzzify this thread's 4 elems: exp(-z^2) = ex2(-(x*a - c*a)^2) ----
    {
        const float* xs = x + (size_t)e0 * N_IN;   // 24 contiguous floats
        float xv[4][N_IN];
        #pragma unroll
        for (int e = 0; e < 4; e++)
            #pragma unroll
            for (int i = 0; i < N_IN; i++)
                xv[e][i] = __ldg(&xs[e * N_IN + i]);

        #pragma unroll
        for (int i = 0; i < N_IN; i++) {
            #pragma unroll
            for (int j = 0; j < N_MF; j++) {
                float2 cs = s_cs[i * N_MF + j];      // LDS.64 broadcast
                float t0 = fmaf(xv[0][i], cs.y, -cs.x);
                float t1 = fmaf(xv[1][i], cs.y, -cs.x);
                float t2 = fmaf(xv[2][i], cs.y, -cs.x);
                float t3 = fmaf(xv[3][i], cs.y, -cs.x);
                __half2 lo = __floats2half2_rn(ex2(-t0 * t0), ex2(-t1 * t1));
                __half2 hi = __floats2half2_rn(ex2(-t2 * t2), ex2(-t3 * t3));
                s_fuzz[(i * N_MF + j) * TPB + tid] =
                    make_uint2(*reinterpret_cast<uint32_t*>(&lo),
                               *reinterpret_cast<uint32_t*>(&hi));
            }
        }
    }
    __syncthreads();

    // ---- rule loop: 6 LDS.64 gathers + 3 broadcasts per rule, 128 elems ----
    const char* fb = reinterpret_cast<const char*>(s_fuzz) + tid * 8;
    u64 l1A = 0, d0A = 0, d1A = 0;   // elems e0,e1
    u64 l1B = 0, d0B = 0, d1B = 0;   // elems e2,e3

    #pragma unroll 2
    for (int k = 0; k < RPS; k++) {
        const uint4      pa = s_pkA[k];     // LDS.128 broadcast
        const uint2      pb = s_pkB[k];     // LDS.64  broadcast
        const ulonglong2 ow = s_owd[k];     // LDS.128 broadcast

        uint2 f0 = *reinterpret_cast<const uint2*>(fb + pa.x);
        uint2 f1 = *reinterpret_cast<const uint2*>(fb + pa.y);
        uint2 f2 = *reinterpret_cast<const uint2*>(fb + pa.z);
        uint2 f3 = *reinterpret_cast<const uint2*>(fb + pa.w);
        uint2 f4 = *reinterpret_cast<const uint2*>(fb + pb.x);
        uint2 f5 = *reinterpret_cast<const uint2*>(fb + pb.y);

        __half2 mA = __hmin2(__hmin2(__hmin2(*(__half2*)&f0.x, *(__half2*)&f1.x),
                                     __hmin2(*(__half2*)&f2.x, *(__half2*)&f3.x)),
                             __hmin2(*(__half2*)&f4.x, *(__half2*)&f5.x));
        __half2 mB = __hmin2(__hmin2(__hmin2(*(__half2*)&f0.y, *(__half2*)&f1.y),
                                     __hmin2(*(__half2*)&f2.y, *(__half2*)&f3.y)),
                             __hmin2(*(__half2*)&f4.y, *(__half2*)&f5.y));

        u64 wA = pack2(__low2float(mA), __high2float(mA));
        u64 wB = pack2(__low2float(mB), __high2float(mB));

        l1A = add2(l1A, wA);            l1B = add2(l1B, wB);
        d0A = fma2(wA, ow.x, d0A);      d0B = fma2(wB, ow.x, d0B);
        d1A = fma2(wA, ow.y, d1A);      d1B = fma2(wB, ow.y, d1B);
    }

    // ---- write partials: 4 consecutive float4 = 64B coalesced ----
    {
        float l0, l1, d00, d01, d10, d11;
        float4* p = &g_partial[split * B_TOT + e0];
        unpack2(l0, l1, l1A); unpack2(d00, d01, d0A); unpack2(d10, d11, d1A);
        p[0] = make_float4(l0, d00, d10, 0.f);
        p[1] = make_float4(l1, d01, d11, 0.f);
        unpack2(l0, l1, l1B); unpack2(d00, d01, d0B); unpack2(d10, d11, d1B);
        p[2] = make_float4(l0, d00, d10, 0.f);
        p[3] = make_float4(l1, d01, d11, 0.f);
    }

    // ---- last-block finalize (deterministic fixed-order summation) ----
    __threadfence();
    __syncthreads();
    if (tid == 0) {
        int old = atomicAdd(&g_cnt[grp], 1);
        s_flag = (old == NSPLIT - 1);
    }
    __syncthreads();

    if (s_flag) {
        __threadfence();
        #pragma unroll
        for (int e = 0; e < 4; e++) {
            const int b = e0 + e;
            float l = 0.f, s0 = 0.f, s1 = 0.f;
            #pragma unroll
            for (int s = 0; s < NSPLIT; s++) {
                float4 p = __ldcg(&g_partial[s * B_TOT + b]);
                l += p.x; s0 += p.y; s1 += p.z;
            }
            float inv = __fdividef(1.0f, fmaxf(l, EPS_F));
            float o0 = tanhf(s0 * inv) * 4.0f;            // scale 4.0, center 0.0
            float o1 = tanhf(s1 * inv) * 0.75f + 0.75f;   // scale .75, center .75
            reinterpret_cast<float2*>(out)[b] = make_float2(o0, o1);
        }
        if (tid == 0) g_cnt[grp] = 0;   // reset for next graph replay
    }
}

// ---------------------------------------------------------------------------
extern "C" void kernel_launch(void* const* d_in, const int* in_sizes, int n_in,
                              void* d_out, int out_size) {
    const float* x            = (const float*)d_in[0];
    const float* mf_centers   = (const float*)d_in[1];
    const float* mf_scales    = (const float*)d_in[2];
    const float* out_centers  = (const float*)d_in[3];
    const int*   input_rules  = (const int*)d_in[4];
    const int*   output_rules = (const int*)d_in[5];

    dim3 grid(NGROUP, NSPLIT);
    anfis_fused_kernel<<<grid, TPB>>>(x, mf_centers, mf_scales, out_centers,
                                      input_rules, output_rules, (float*)d_out);
}

// round 10
// speedup vs baseline: 1.2405x; 1.2405x over previous
#include <cuda_runtime.h>
#include <cuda_fp16.h>
#include <stdint.h>

#define B_TOT   16384
#define N_IN    6
#define N_MF    5
#define N_FUZZ  30
#define N_RULES 2048
#define NSPLIT  16
#define RPS     (N_RULES / NSPLIT)   // 128 rules per split
#define TPB     128
#define EPB     256                  // 2 elems per thread (half2)
#define NGROUP  (B_TOT / EPB)        // 64
#define EPS_F   1e-12f
#define SQRT_LOG2E 1.2011224087864498f   // sqrt(log2(e))

// Scratch (__device__ globals: no allocation allowed)
__device__ float4 g_partial[NSPLIT * B_TOT];   // {l1, d0, d1, pad}
__device__ int    g_cnt[NGROUP];               // zero-init; reset after use

static __device__ __forceinline__ float ex2(float v) {
    float r; asm("ex2.approx.ftz.f32 %0, %1;" : "=f"(r) : "f"(v)); return r;
}

// ---------------------------------------------------------------------------
// Single fused kernel (R6 structure; rule metadata compressed to ONE 16B
// record per rule -> single LDS.128 broadcast instead of two).
//  - Fuzz table in SMEM as half2 {fuzz[b0], fuzz[b1]}, b1 = b0+128; one
//    LDS.32 gather serves 2 elems; bank = tid mod 32 -> conflict-free.
//  - Rule record uint4: {x: 4 bytes of 2*idx, y: 2 bytes of 2*idx,
//    z: ow0 bits, w: ow1 bits}. __byte_perm(0, word, 0x004k) produces
//    (2*idx)<<8 == idx<<9 == the 512B-row byte offset in ONE instruction.
//  - Fuzzify: 1 FFMA + 1 FMUL + 1 ex2.approx per Gaussian via {c*a, a}.
//  - Last-arriving split block per group finalizes (deterministic order).
// ---------------------------------------------------------------------------
__global__ __launch_bounds__(TPB) void anfis_fused_kernel(
    const float* __restrict__ x,
    const float* __restrict__ mf_centers,
    const float* __restrict__ mf_scales,
    const float* __restrict__ out_centers,
    const int*   __restrict__ input_rules,
    const int*   __restrict__ output_rules,
    float* __restrict__ out)
{
    __shared__ __half2 s_fuzz[N_FUZZ * TPB];  // 15 KB
    __shared__ uint4   s_pk[RPS];             // 2 KB: one record per rule
    __shared__ float2  s_cs[N_FUZZ];          // {c*a, a}
    __shared__ int     s_flag;

    const int tid   = threadIdx.x;
    const int grp   = blockIdx.x;
    const int split = blockIdx.y;
    const int b0    = grp * EPB + tid;
    const int b1    = b0 + TPB;

    // ---- stage this split's rules: byte-packed 2*idx + fp32 ow ----
    if (tid < RPS) {
        const int r = split * RPS + tid;
        const int* ir = input_rules + r * N_IN;
        unsigned w0 = ((unsigned)ir[0] * 2)
                    | (((unsigned)ir[1] * 2) << 8)
                    | (((unsigned)ir[2] * 2) << 16)
                    | (((unsigned)ir[3] * 2) << 24);
        unsigned w1 = ((unsigned)ir[4] * 2)
                    | (((unsigned)ir[5] * 2) << 8);
        float ow0 = out_centers[output_rules[r * 2 + 0]];
        float ow1 = out_centers[output_rules[r * 2 + 1]];
        s_pk[tid] = make_uint4(w0, w1, __float_as_uint(ow0), __float_as_uint(ow1));
    }
    // ---- membership-function constants: a = sqrt(log2e)/s ----
    if (tid < N_FUZZ) {
        float c = mf_centers[tid];
        float s = mf_scales[tid];
        float a = __fdividef(SQRT_LOG2E, s);
        s_cs[tid] = make_float2(c * a, a);
    }
    __syncthreads();

    // ---- fuzzify both batch elems: exp(-z^2) = ex2(-(x*a - c*a)^2) ----
    {
        float xa[N_IN], xb[N_IN];
        #pragma unroll
        for (int i = 0; i < N_IN; i++) {
            xa[i] = x[b0 * N_IN + i];
            xb[i] = x[b1 * N_IN + i];
        }
        #pragma unroll
        for (int i = 0; i < N_IN; i++) {
            #pragma unroll
            for (int j = 0; j < N_MF; j++) {
                float2 cs = s_cs[i * N_MF + j];      // LDS.64 broadcast
                float ta = fmaf(xa[i], cs.y, -cs.x);
                float tb = fmaf(xb[i], cs.y, -cs.x);
                s_fuzz[(i * N_MF + j) * TPB + tid] =
                    __floats2half2_rn(ex2(-ta * ta), ex2(-tb * tb));
            }
        }
    }
    __syncthreads();

    // ---- rule loop: 1 LDS.128 bcast + 6 LDS.32 gathers per rule ----
    const char* fb = reinterpret_cast<const char*>(s_fuzz) + tid * 4;
    float la = 0.f, lb = 0.f;      // l1 accumulators (weights >= 0)
    float d0a = 0.f, d0b = 0.f;
    float d1a = 0.f, d1b = 0.f;

    #pragma unroll 4
    for (int k = 0; k < RPS; k++) {
        const uint4 pk = s_pk[k];                  // single LDS.128 broadcast

        // __byte_perm(0, w, 0x004k): result = byte_k(w) << 8 = (2*idx)<<8 = idx<<9
        __half2 f0 = *reinterpret_cast<const __half2*>(fb + __byte_perm(0u, pk.x, 0x0040));
        __half2 f1 = *reinterpret_cast<const __half2*>(fb + __byte_perm(0u, pk.x, 0x0050));
        __half2 f2 = *reinterpret_cast<const __half2*>(fb + __byte_perm(0u, pk.x, 0x0060));
        __half2 f3 = *reinterpret_cast<const __half2*>(fb + __byte_perm(0u, pk.x, 0x0070));
        __half2 f4 = *reinterpret_cast<const __half2*>(fb + __byte_perm(0u, pk.y, 0x0040));
        __half2 f5 = *reinterpret_cast<const __half2*>(fb + __byte_perm(0u, pk.y, 0x0050));

        __half2 w = __hmin2(__hmin2(__hmin2(f0, f1), __hmin2(f2, f3)),
                            __hmin2(f4, f5));

        float wa = __low2float(w);
        float wb = __high2float(w);
        float ow0 = __uint_as_float(pk.z);
        float ow1 = __uint_as_float(pk.w);

        la += wa;                      lb += wb;
        d0a = fmaf(wa, ow0, d0a);      d0b = fmaf(wb, ow0, d0b);
        d1a = fmaf(wa, ow1, d1a);      d1b = fmaf(wb, ow1, d1b);
    }

    // ---- write partials ----
    g_partial[split * B_TOT + b0] = make_float4(la, d0a, d1a, 0.f);
    g_partial[split * B_TOT + b1] = make_float4(lb, d0b, d1b, 0.f);

    // ---- last-block finalize (deterministic fixed-order summation) ----
    __threadfence();
    __syncthreads();
    if (tid == 0) {
        int old = atomicAdd(&g_cnt[grp], 1);
        s_flag = (old == NSPLIT - 1);
    }
    __syncthreads();

    if (s_flag) {
        __threadfence();
        #pragma unroll
        for (int e = 0; e < 2; e++) {
            const int b = (e == 0) ? b0 : b1;
            float l = 0.f, s0 = 0.f, s1 = 0.f;
            #pragma unroll
            for (int s = 0; s < NSPLIT; s++) {
                float4 p = __ldcg(&g_partial[s * B_TOT + b]);
                l += p.x; s0 += p.y; s1 += p.z;
            }
            float inv = __fdividef(1.0f, fmaxf(l, EPS_F));
            float o0 = tanhf(s0 * inv) * 4.0f;            // scale 4.0, center 0.0
            float o1 = tanhf(s1 * inv) * 0.75f + 0.75f;   // scale .75, center .75
            reinterpret_cast<float2*>(out)[b] = make_float2(o0, o1);
        }
        if (tid == 0) g_cnt[grp] = 0;   // reset for next graph replay
    }
}

// ---------------------------------------------------------------------------
extern "C" void kernel_launch(void* const* d_in, const int* in_sizes, int n_in,
                              void* d_out, int out_size) {
    const float* x            = (const float*)d_in[0];
    const float* mf_centers   = (const float*)d_in[1];
    const float* mf_scales    = (const float*)d_in[2];
    const float* out_centers  = (const float*)d_in[3];
    const int*   input_rules  = (const int*)d_in[4];
    const int*   output_rules = (const int*)d_in[5];

    dim3 grid(NGROUP, NSPLIT);
    anfis_fused_kernel<<<grid, TPB>>>(x, mf_centers, mf_scales, out_centers,
                                      input_rules, output_rules, (float*)d_out);
}